// round 14
// baseline (speedup 1.0000x reference)
#include <cuda_runtime.h>
#include <cuda_fp16.h>
#include <cstdint>

#define B_ 16
#define N_ 2048
#define F_ 2048
#define E_ 128
#define K_ 10
#define R_ 2
#define ZSPLIT 16

// ---------------- device scratch (static, no runtime allocation) ----------
__device__ float g_h[R_][2][B_][E_];        // hop vectors (h1,h2) per rule
__device__ float g_esq[B_][N_];             // entity squared norms
__device__ float g_cbias[R_][B_][F_];       // hop-1 fact bias
__device__ float g_cb2[R_][B_][F_];         // hop-2 fact bias
__device__ unsigned g_s0key[B_];            // scores_0 ordered-int atomic max
__device__ unsigned g_Lkey[R_][B_][N_];     // hop-1 log scores (ordered-uint)
__device__ int   g_zidx[R_][B_][K_];
__device__ float g_zlog[R_][B_][K_];
__device__ float g_s2part[R_][B_][ZSPLIT][K_];

// fp16 planes (round-to-nearest)
__device__ __half g_ehi[B_ * N_ * E_];
__device__ __half g_f1hi[B_ * F_ * E_];
__device__ __half g_f2hi[B_ * F_ * E_];

// ---------------- helpers ---------------------------------------------------
__device__ __forceinline__ float warp_sum(float v) {
#pragma unroll
    for (int o = 16; o > 0; o >>= 1) v += __shfl_xor_sync(0xffffffffu, v, o);
    return v;
}
__device__ __forceinline__ float hsum16(float v) {
#pragma unroll
    for (int o = 8; o > 0; o >>= 1) v += __shfl_xor_sync(0xffffffffu, v, o);
    return v;
}
__device__ __forceinline__ float dot4(float4 a, float4 b) {
    return a.x * b.x + a.y * b.y + a.z * b.z + a.w * b.w;
}
__device__ __forceinline__ unsigned fenc(float v) {
    unsigned u = __float_as_uint(v);
    return (u & 0x80000000u) ? ~u : (u | 0x80000000u);
}
__device__ __forceinline__ float fdec(unsigned k) {
    return (k & 0x80000000u) ? __uint_as_float(k ^ 0x80000000u) : __uint_as_float(~k);
}
__device__ __forceinline__ uint32_t smem_u32(const void* p) {
    uint32_t a;
    asm("{ .reg .u64 t; cvta.to.shared.u64 t, %1; cvt.u32.u64 %0, t; }" : "=r"(a) : "l"(p));
    return a;
}
__device__ __forceinline__ unsigned pack_half2(float a, float b) {
    __half2 h = __halves2half2(__float2half_rn(a), __float2half_rn(b));
    return *(unsigned*)&h;
}

// ---------------- portable tensor-core / async-copy PTX ----------------------
__device__ __forceinline__ void cp16(uint32_t s, const void* g) {
    asm volatile("cp.async.cg.shared.global [%0], [%1], 16;" :: "r"(s), "l"(g));
}
__device__ __forceinline__ void cpcommit() { asm volatile("cp.async.commit_group;"); }
template <int NN>
__device__ __forceinline__ void cpwait() {
    asm volatile("cp.async.wait_group %0;" :: "n"(NN));
}
__device__ __forceinline__ void ldsm4(uint32_t& r0, uint32_t& r1, uint32_t& r2, uint32_t& r3,
                                      uint32_t a) {
    asm volatile("ldmatrix.sync.aligned.m8n8.x4.shared.b16 {%0,%1,%2,%3}, [%4];"
                 : "=r"(r0), "=r"(r1), "=r"(r2), "=r"(r3) : "r"(a));
}
__device__ __forceinline__ void mma16816(float* c, const uint32_t* a, const uint32_t* b) {
    asm volatile(
        "mma.sync.aligned.m16n8k16.row.col.f32.f16.f16.f32 "
        "{%0,%1,%2,%3},{%4,%5,%6,%7},{%8,%9},{%0,%1,%2,%3};"
        : "+f"(c[0]), "+f"(c[1]), "+f"(c[2]), "+f"(c[3])
        : "r"(a[0]), "r"(a[1]), "r"(a[2]), "r"(a[3]), "r"(b[0]), "r"(b[1]));
}
// swizzled tile offset: rows x 128 fp16 (256B rows, 16-byte chunks, XOR swizzle)
__device__ __forceinline__ uint32_t swz(int row, int chunk) {
    return (uint32_t)row * 256u + (uint32_t)((chunk ^ (row & 7)) * 16);
}

// ------ merged prep: entity fp16 + norms + Lkey init, and hop vectors --------
__global__ void k_prep(const float* __restrict__ ent, const float* __restrict__ rel,
                       const float* __restrict__ W, const float* __restrict__ hb) {
    int tid = threadIdx.x;
    if (blockIdx.x < 4096) {
        size_t i = ((size_t)blockIdx.x * 256 + tid) * 4;
        float4 v = *(const float4*)(ent + i);
        uint2 uh = {pack_half2(v.x, v.y), pack_half2(v.z, v.w)};
        *(uint2*)(g_ehi + i) = uh;
        float s = warp_sum(dot4(v, v));
        if ((tid & 31) == 0) {
            int gw = blockIdx.x * 8 + (tid >> 5);
            ((float*)g_esq)[gw] = s;
            unsigned init = fenc(-3e30f);
            int b = gw >> 11, n = gw & (N_ - 1);
            g_Lkey[0][b][n] = init;
            g_Lkey[1][b][n] = init;
        }
    } else {
        int idx = blockIdx.x - 4096;  // 0..63
        int b = idx & 15, h = (idx >> 4) & 1, r = idx >> 5;
        if (tid >= E_) return;
        int e = tid;
        if (e == 0 && h == 0 && r == 0) g_s0key[b] = fenc(-3e30f);
        const float* w = W + (size_t)((r * 2 + h) * E_) * E_ + e;
        const float* rb = rel + b * E_;
        float s = hb[(r * 2 + h) * E_ + e];
#pragma unroll 8
        for (int i = 0; i < E_; i++) s += rb[i] * w[(size_t)i * E_];
        g_h[r][h][b][e] = s;
    }
}

// -- per-fact biases + fused scores_0 + fused fp16 fact conversion -----------
// 512 blocks x 8 warps; each warp loops 8 facts (2 per iter), constants hoisted
__global__ void k_cbias(const float* __restrict__ rel, const float* __restrict__ arg1,
                        const float* __restrict__ arg2, const float* __restrict__ fr,
                        const float* __restrict__ fa1, const float* __restrict__ fa2,
                        const int* __restrict__ nbf) {
    int tid = threadIdx.x, lane = tid & 31, hl = lane & 15, sub = lane >> 4;
    int wg = blockIdx.x * 8 + (tid >> 5);  // 0..4095
    int b = wg >> 8;
    int fbase = (wg & 255) * 8;
    const float4* Q;
#define LD2(dst0, dst1, base) Q = (const float4*)(base); float4 dst0 = Q[0], dst1 = Q[1];
    LD2(h00a, h00b, &g_h[0][0][b][hl * 8]);
    LD2(h10a, h10b, &g_h[1][0][b][hl * 8]);
    LD2(h01a, h01b, &g_h[0][1][b][hl * 8]);
    LD2(h11a, h11b, &g_h[1][1][b][hl * 8]);
    LD2(qra, qrb, rel + b * E_ + hl * 8);
    LD2(a1a, a1b, arg1 + b * E_ + hl * 8);
    LD2(a2a, a2b, arg2 + b * E_ + hl * 8);
#undef LD2
    float h00s = dot4(h00a, h00a) + dot4(h00b, h00b);
    float h10s = dot4(h10a, h10a) + dot4(h10b, h10b);
    float h01s = dot4(h01a, h01a) + dot4(h01b, h01b);
    float h11s = dot4(h11a, h11a) + dot4(h11b, h11b);
    float qrs = dot4(qra, qra) + dot4(qrb, qrb);
    float a1s = dot4(a1a, a1a) + dot4(a1b, a1b);
    float a2s = dot4(a2a, a2a) + dot4(a2b, a2b);
    int nb = nbf[b];

    for (int it = 0; it < 4; ++it) {
        int f = fbase + it * 2 + sub;
        size_t off = ((size_t)b * F_ + f) * E_ + hl * 8;
        const float4* PR = (const float4*)(fr + off);
        const float4* P1 = (const float4*)(fa1 + off);
        const float4* P2 = (const float4*)(fa2 + off);
        float4 vr0 = PR[0], vr1 = PR[1];
        float4 v10 = P1[0], v11 = P1[1];
        float4 v20 = P2[0], v21 = P2[1];
        uint4 c1 = {pack_half2(v10.x, v10.y), pack_half2(v10.z, v10.w),
                    pack_half2(v11.x, v11.y), pack_half2(v11.z, v11.w)};
        uint4 c2 = {pack_half2(v20.x, v20.y), pack_half2(v20.z, v20.w),
                    pack_half2(v21.x, v21.y), pack_half2(v21.z, v21.w)};
        *(uint4*)(g_f1hi + off) = c1;
        *(uint4*)(g_f2hi + off) = c2;
        float nsum = dot4(vr0, vr0) + dot4(vr1, vr1) + dot4(v10, v10) + dot4(v11, v11) +
                     dot4(v20, v20) + dot4(v21, v21);
        float a1v1 = dot4(a1a, v10) + dot4(a1b, v11);
        float a2v1 = dot4(a2a, v10) + dot4(a2b, v11);
        float a1v2 = dot4(a1a, v20) + dot4(a1b, v21);
        float a2v2 = dot4(a2a, v20) + dot4(a2b, v21);
        float p0 = nsum + h00s + a1s - 2.f * (dot4(h00a, vr0) + dot4(h00b, vr1) + a1v1);
        float p1 = nsum + h10s + a1s - 2.f * (dot4(h10a, vr0) + dot4(h10b, vr1) + a1v2);
        float q0 = nsum + h01s + a2s - 2.f * (dot4(h01a, vr0) + dot4(h01b, vr1) + a2v2);
        float q1 = nsum + h11s + a2s - 2.f * (dot4(h11a, vr0) + dot4(h11b, vr1) + a2v1);
        float s = nsum + qrs + a1s + a2s -
                  2.f * (dot4(qra, vr0) + dot4(qrb, vr1) + a1v1 + a2v2);
        p0 = hsum16(p0);
        p1 = hsum16(p1);
        q0 = hsum16(q0);
        q1 = hsum16(q1);
        s = hsum16(s);
        if (hl == 0) {
            bool valid = f < nb;
            g_cbias[0][b][f] = valid ? -0.5f * p0 : -3e30f;
            g_cbias[1][b][f] = valid ? -0.5f * p1 : -3e30f;
            g_cb2[0][b][f] = valid ? -0.5f * q0 : -3e30f;
            g_cb2[1][b][f] = valid ? -0.5f * q1 : -3e30f;
            if (valid) atomicMax(&g_s0key[b], fenc(-0.5f * s));
        }
    }
}

// ------- heavy max-plus GEMM via mma.sync (single-pass fp16) -----------------
// grid (nt=16, b=16, r*4+fq=8); 256 threads / 8 warps, CTA tile 128x128,
// warp grid 4m x 2n (warp tile 32x64); A + cbias + B all via cp.async
#define OFF_AHI 0
#define OFF_B0 32768
#define OFF_CB 98304
#define SMEM_MG 99328

__global__ __launch_bounds__(256, 2) void k_maxgemm(const int* __restrict__ nbe) {
    extern __shared__ char smem[];
    uint32_t sb = smem_u32(smem);
    const int tid = threadIdx.x, lane = tid & 31, wid = tid >> 5;
    const int wm = (wid & 3) * 32, wn = (wid >> 2) * 64;
    const int nt = blockIdx.x, b = blockIdx.y;
    const int r = blockIdx.z >> 2, fq = blockIdx.z & 3;

    const __half* ehi = g_ehi + ((size_t)b * N_ + nt * 128) * E_;
    const __half* fhi = ((r == 0) ? g_f2hi : g_f1hi) + (size_t)b * F_ * E_;
    const float* cb = &g_cbias[r][b][0];

    // hoisted ldsm row bases + swizzle keys (invariant across k-steps/tiles)
    uint32_t aBase[2], bOff[4];
    int aX[2], bX[4];
#pragma unroll
    for (int i = 0; i < 2; i++) {
        int row = wm + i * 16 + (lane & 15);
        aBase[i] = sb + OFF_AHI + (uint32_t)row * 256u;
        aX[i] = row & 7;
    }
#pragma unroll
    for (int p = 0; p < 4; p++) {
        int row = wn + p * 16 + (lane & 15);
        bOff[p] = (uint32_t)row * 256u;
        bX[p] = row & 7;
    }

    // resident entity tile (128 rows) via cp.async, swizzled
#pragma unroll
    for (int it = 0; it < 8; ++it) {
        int i = tid + it * 256;
        int row = i >> 4, ch = i & 15;
        cp16(sb + OFF_AHI + swz(row, ch), ehi + (size_t)row * E_ + ch * 8);
    }
    cpcommit();

    auto issueB = [&](int ft, int buf) {
        uint32_t base = sb + OFF_B0 + buf * 32768;
        const __half* sh = fhi + (size_t)ft * 128 * E_;
#pragma unroll
        for (int it = 0; it < 8; ++it) {
            int i = tid + it * 256;
            int row = i >> 4, ch = i & 15;
            cp16(base + swz(row, ch), sh + (size_t)row * E_ + ch * 8);
        }
        if (tid < 32) cp16(sb + OFF_CB + buf * 512 + tid * 16, cb + ft * 128 + tid * 4);
    };
    issueB(fq * 4, 0);
    cpcommit();

    float rmax[4];
#pragma unroll
    for (int i = 0; i < 4; i++) rmax[i] = -3e30f;

    for (int t = 0; t < 4; ++t) {
        int ft = fq * 4 + t;
        cpwait<0>();
        __syncthreads();  // buffer t&1 ready; all warps done with the other buffer
        if (t + 1 < 4) {
            issueB(ft + 1, (t + 1) & 1);
            cpcommit();
        }

        float acc[2][8][4];
#pragma unroll
        for (int i = 0; i < 2; i++)
#pragma unroll
            for (int j = 0; j < 8; j++)
#pragma unroll
                for (int q = 0; q < 4; q++) acc[i][j][q] = 0.f;

        uint32_t bbase = sb + OFF_B0 + (t & 1) * 32768;
#pragma unroll
        for (int ks = 0; ks < 8; ++ks) {
            int kc = ks * 2 + (lane >> 4);
            uint32_t ah[2][4];
#pragma unroll
            for (int i = 0; i < 2; i++)
                ldsm4(ah[i][0], ah[i][1], ah[i][2], ah[i][3],
                      aBase[i] + (uint32_t)((kc ^ aX[i]) << 4));
            uint32_t bh[8][2];
#pragma unroll
            for (int p = 0; p < 4; p++) {
                uint32_t r0, r1, r2, r3;
                ldsm4(r0, r1, r2, r3, bbase + bOff[p] + (uint32_t)((kc ^ bX[p]) << 4));
                bh[2 * p][0] = r0; bh[2 * p][1] = r2;
                bh[2 * p + 1][0] = r1; bh[2 * p + 1][1] = r3;
            }
#pragma unroll
            for (int i = 0; i < 2; i++)
#pragma unroll
                for (int j = 0; j < 8; j++) mma16816(acc[i][j], ah[i], bh[j]);
        }
        // epilogue: add cbias (smem broadcast), fold running row-max
        const float* cbs = (const float*)(smem + OFF_CB + (t & 1) * 512);
#pragma unroll
        for (int j = 0; j < 8; j++) {
            float2 cc = *(const float2*)(cbs + wn + j * 8 + 2 * (lane & 3));
#pragma unroll
            for (int i = 0; i < 2; i++) {
                rmax[2 * i] = fmaxf(rmax[2 * i],
                                    fmaxf(acc[i][j][0] + cc.x, acc[i][j][1] + cc.y));
                rmax[2 * i + 1] = fmaxf(rmax[2 * i + 1],
                                        fmaxf(acc[i][j][2] + cc.x, acc[i][j][3] + cc.y));
            }
        }
    }

    // cross-thread row-max reduction (reuse smem): 8 partials per row
    __syncthreads();
    float* Red = (float*)smem;
#pragma unroll
    for (int i = 0; i < 2; i++)
#pragma unroll
        for (int h = 0; h < 2; h++) {
            int row = wm + i * 16 + h * 8 + (lane >> 2);
            Red[row * 9 + (wid >> 2) * 4 + (lane & 3)] = rmax[2 * i + h];
        }
    __syncthreads();
    if (tid < 128) {
        float m = -3e30f;
#pragma unroll
        for (int t = 0; t < 8; t++) m = fmaxf(m, Red[tid * 9 + t]);
        int gn = nt * 128 + tid;
        float Lv = m - 0.5f * g_esq[b][gn];
        if (gn < nbe[b]) atomicMax(&g_Lkey[r][b][gn], fenc(Lv));
    }
}

// ---- beam: per-(b,r,z) block — warp-local top-K, then hop-2 partial max -----
// 128 threads / 4 warps; ZSPLIT=16 (128 facts per block)
__global__ void k_beam(const float* __restrict__ ent) {
    int b = blockIdx.x, r = blockIdx.y, z = blockIdx.z, tid = threadIdx.x;
    int lane = tid & 31, wid = tid >> 5;
    __shared__ __align__(16) float zs[K_][E_];
    __shared__ __align__(16) float red[K_][129];
    __shared__ float mv[4 * K_];
    __shared__ int mi[4 * K_];
    __shared__ float szlog[K_];
    __shared__ int szidx[K_];

    // ---- phase 1a: warp-local top-K over 512 elements (no block syncs) ----
    float v[16];
#pragma unroll
    for (int j = 0; j < 16; j++) v[j] = fdec(g_Lkey[r][b][wid * 512 + 32 * j + lane]);
    for (int kk = 0; kk < K_; kk++) {
        float bv = -3.4e38f;
        int bi = 0;
#pragma unroll
        for (int j = 0; j < 16; j++)
            if (v[j] > bv) { bv = v[j]; bi = wid * 512 + 32 * j + lane; }
#pragma unroll
        for (int o = 16; o > 0; o >>= 1) {
            float ov = __shfl_xor_sync(0xffffffffu, bv, o);
            int oi = __shfl_xor_sync(0xffffffffu, bi, o);
            if (ov > bv || (ov == bv && oi < bi)) { bv = ov; bi = oi; }
        }
        if (lane == 0) { mv[wid * K_ + kk] = bv; mi[wid * K_ + kk] = bi; }
        int rel0 = bi - wid * 512;
        if ((rel0 & 31) == lane) v[rel0 >> 5] = -3.4e38f;
    }
    __syncthreads();

    // ---- phase 1b: warp 0 merges 40 candidates ----
    if (wid == 0) {
        float cv0 = mv[lane];
        int ci0 = mi[lane];
        float cv1 = (lane < 8) ? mv[lane + 32] : -3.4e38f;
        int ci1 = (lane < 8) ? mi[lane + 32] : -1;
        for (int kk = 0; kk < K_; kk++) {
            float bv;
            int bi;
            if (cv0 > cv1 || (cv0 == cv1 && ci0 < ci1)) { bv = cv0; bi = ci0; }
            else { bv = cv1; bi = ci1; }
#pragma unroll
            for (int o = 16; o > 0; o >>= 1) {
                float ov = __shfl_xor_sync(0xffffffffu, bv, o);
                int oi = __shfl_xor_sync(0xffffffffu, bi, o);
                if (ov > bv || (ov == bv && oi < bi)) { bv = ov; bi = oi; }
            }
            if (lane == 0) { szlog[kk] = bv; szidx[kk] = bi; }
            if (ci0 == bi) cv0 = -3.4e38f;
            if (ci1 == bi) cv1 = -3.4e38f;
        }
    }
    __syncthreads();
    if (z == 0 && tid < K_) {  // publish once for k_final
        g_zidx[r][b][tid] = szidx[tid];
        g_zlog[r][b][tid] = szlog[tid];
    }

    // ---- phase 2: hop-2 partial max over this z-slice of 128 facts ----
    for (int i = tid; i < K_ * E_; i += 128) {
        int k = i >> 7, e = i & 127;
        zs[k][e] = ent[((size_t)b * N_ + szidx[k]) * E_ + e];
    }
    __syncthreads();
    const __half* fy = ((r == 0) ? g_f1hi : g_f2hi) + (size_t)b * F_ * E_;
    int f = z * 128 + tid;
    float c = g_cb2[r][b][f];
    const uint4* row = (const uint4*)(fy + (size_t)f * E_);
    float d[K_];
#pragma unroll
    for (int k = 0; k < K_; k++) d[k] = 0.f;
#pragma unroll 2
    for (int e8 = 0; e8 < 16; e8++) {
        uint4 u = row[e8];
        float2 w0 = __half22float2(*(__half2*)&u.x);
        float2 w1 = __half22float2(*(__half2*)&u.y);
        float2 w2 = __half22float2(*(__half2*)&u.z);
        float2 w3 = __half22float2(*(__half2*)&u.w);
#pragma unroll
        for (int k = 0; k < K_; k++) {
            float4 z0 = ((const float4*)zs[k])[e8 * 2];
            float4 z1 = ((const float4*)zs[k])[e8 * 2 + 1];
            d[k] += w0.x * z0.x + w0.y * z0.y + w1.x * z0.z + w1.y * z0.w +
                    w2.x * z1.x + w2.y * z1.y + w3.x * z1.z + w3.y * z1.w;
        }
    }
#pragma unroll
    for (int k = 0; k < K_; k++) red[k][tid] = d[k] + c;
    __syncthreads();
    for (int k = wid; k < K_; k += 4) {
        float m = -3e30f;
#pragma unroll
        for (int j = 0; j < 4; j++) m = fmaxf(m, red[k][lane + 32 * j]);
#pragma unroll
        for (int o = 16; o > 0; o >>= 1) m = fmaxf(m, __shfl_xor_sync(0xffffffffu, m, o));
        if (lane == 0) g_s2part[r][b][z][k] = m;
    }
}

// ---------------- final combine ----------------------------------------------
__global__ void k_final(float* __restrict__ out) {
    int b = threadIdx.x;
    if (b >= B_) return;
    float res = expf(fdec(g_s0key[b]));
#pragma unroll
    for (int r = 0; r < R_; r++)
#pragma unroll
        for (int k = 0; k < K_; k++) {
            float m = -3e30f;
            for (int z = 0; z < ZSPLIT; z++) m = fmaxf(m, g_s2part[r][b][z][k]);
            float s2 = m - 0.5f * g_esq[b][g_zidx[r][b][k]];
            res = fmaxf(res, expf(fminf(s2, g_zlog[r][b][k])));
        }
    out[b] = res;
}

// ---------------- launch -------------------------------------------------------
extern "C" void kernel_launch(void* const* d_in, const int* in_sizes, int n_in,
                              void* d_out, int out_size) {
    (void)in_sizes; (void)n_in; (void)out_size;
    const float* rel = (const float*)d_in[0];
    const float* arg1 = (const float*)d_in[1];
    const float* arg2 = (const float*)d_in[2];
    const float* fr = (const float*)d_in[3];
    const float* fa1 = (const float*)d_in[4];
    const float* fa2 = (const float*)d_in[5];
    const float* ent = (const float*)d_in[6];
    const float* W = (const float*)d_in[7];
    const float* hb = (const float*)d_in[8];
    const int* nbf = (const int*)d_in[9];
    const int* nbe = (const int*)d_in[10];
    float* out = (float*)d_out;

    cudaFuncSetAttribute(k_maxgemm, cudaFuncAttributeMaxDynamicSharedMemorySize, SMEM_MG);

    k_prep<<<4160, 256>>>(ent, rel, W, hb);
    k_cbias<<<512, 256>>>(rel, arg1, arg2, fr, fa1, fa2, nbf);
    k_maxgemm<<<dim3(N_ / 128, B_, 4 * R_), 256, SMEM_MG>>>(nbe);
    k_beam<<<dim3(B_, R_, ZSPLIT), 128>>>(ent);
    k_final<<<1, 32>>>(out);
}

// round 15
// speedup vs baseline: 1.0152x; 1.0152x over previous
#include <cuda_runtime.h>
#include <cuda_fp16.h>
#include <cstdint>

#define B_ 16
#define N_ 2048
#define F_ 2048
#define E_ 128
#define K_ 10
#define R_ 2
#define ZSPLIT 8

// ---------------- device scratch (static, no runtime allocation) ----------
__device__ float g_h[R_][2][B_][E_];        // hop vectors (h1,h2) per rule
__device__ float g_esq[B_][N_];             // entity squared norms
__device__ float g_cbias[R_][B_][F_];       // hop-1 fact bias
__device__ float g_cb2[R_][B_][F_];         // hop-2 fact bias
__device__ unsigned g_s0key[B_];            // scores_0 ordered-int atomic max
__device__ unsigned g_Lkey[R_][B_][N_];     // hop-1 log scores (ordered-uint)
__device__ int   g_zidx[R_][B_][K_];
__device__ float g_zlog[R_][B_][K_];
__device__ float g_s2part[R_][B_][ZSPLIT][K_];

// fp16 planes (round-to-nearest)
__device__ __half g_ehi[B_ * N_ * E_];
__device__ __half g_f1hi[B_ * F_ * E_];
__device__ __half g_f2hi[B_ * F_ * E_];

// ---------------- helpers ---------------------------------------------------
__device__ __forceinline__ float warp_sum(float v) {
#pragma unroll
    for (int o = 16; o > 0; o >>= 1) v += __shfl_xor_sync(0xffffffffu, v, o);
    return v;
}
__device__ __forceinline__ float hsum16(float v) {
#pragma unroll
    for (int o = 8; o > 0; o >>= 1) v += __shfl_xor_sync(0xffffffffu, v, o);
    return v;
}
__device__ __forceinline__ float dot4(float4 a, float4 b) {
    return a.x * b.x + a.y * b.y + a.z * b.z + a.w * b.w;
}
__device__ __forceinline__ unsigned fenc(float v) {
    unsigned u = __float_as_uint(v);
    return (u & 0x80000000u) ? ~u : (u | 0x80000000u);
}
__device__ __forceinline__ float fdec(unsigned k) {
    return (k & 0x80000000u) ? __uint_as_float(k ^ 0x80000000u) : __uint_as_float(~k);
}
__device__ __forceinline__ uint32_t smem_u32(const void* p) {
    uint32_t a;
    asm("{ .reg .u64 t; cvta.to.shared.u64 t, %1; cvt.u32.u64 %0, t; }" : "=r"(a) : "l"(p));
    return a;
}
__device__ __forceinline__ unsigned pack_half2(float a, float b) {
    __half2 h = __halves2half2(__float2half_rn(a), __float2half_rn(b));
    return *(unsigned*)&h;
}

// ---------------- portable tensor-core / async-copy PTX ----------------------
__device__ __forceinline__ void cp16(uint32_t s, const void* g) {
    asm volatile("cp.async.cg.shared.global [%0], [%1], 16;" :: "r"(s), "l"(g));
}
__device__ __forceinline__ void cpcommit() { asm volatile("cp.async.commit_group;"); }
template <int NN>
__device__ __forceinline__ void cpwait() {
    asm volatile("cp.async.wait_group %0;" :: "n"(NN));
}
__device__ __forceinline__ void ldsm4(uint32_t& r0, uint32_t& r1, uint32_t& r2, uint32_t& r3,
                                      uint32_t a) {
    asm volatile("ldmatrix.sync.aligned.m8n8.x4.shared.b16 {%0,%1,%2,%3}, [%4];"
                 : "=r"(r0), "=r"(r1), "=r"(r2), "=r"(r3) : "r"(a));
}
__device__ __forceinline__ void mma16816(float* c, const uint32_t* a, const uint32_t* b) {
    asm volatile(
        "mma.sync.aligned.m16n8k16.row.col.f32.f16.f16.f32 "
        "{%0,%1,%2,%3},{%4,%5,%6,%7},{%8,%9},{%0,%1,%2,%3};"
        : "+f"(c[0]), "+f"(c[1]), "+f"(c[2]), "+f"(c[3])
        : "r"(a[0]), "r"(a[1]), "r"(a[2]), "r"(a[3]), "r"(b[0]), "r"(b[1]));
}
// swizzled tile offset: rows x 128 fp16 (256B rows, 16-byte chunks, XOR swizzle)
__device__ __forceinline__ uint32_t swz(int row, int chunk) {
    return (uint32_t)row * 256u + (uint32_t)((chunk ^ (row & 7)) * 16);
}

// ------ merged prep: entity fp16 + norms + Lkey init, and hop vectors --------
__global__ void k_prep(const float* __restrict__ ent, const float* __restrict__ rel,
                       const float* __restrict__ W, const float* __restrict__ hb) {
    int tid = threadIdx.x;
    if (blockIdx.x < 4096) {
        size_t i = ((size_t)blockIdx.x * 256 + tid) * 4;
        float4 v = *(const float4*)(ent + i);
        uint2 uh = {pack_half2(v.x, v.y), pack_half2(v.z, v.w)};
        *(uint2*)(g_ehi + i) = uh;
        float s = warp_sum(dot4(v, v));
        if ((tid & 31) == 0) {
            int gw = blockIdx.x * 8 + (tid >> 5);
            ((float*)g_esq)[gw] = s;
            unsigned init = fenc(-3e30f);
            int b = gw >> 11, n = gw & (N_ - 1);
            g_Lkey[0][b][n] = init;
            g_Lkey[1][b][n] = init;
        }
    } else {
        int idx = blockIdx.x - 4096;  // 0..63
        int b = idx & 15, h = (idx >> 4) & 1, r = idx >> 5;
        if (tid >= E_) return;
        int e = tid;
        if (e == 0 && h == 0 && r == 0) g_s0key[b] = fenc(-3e30f);
        const float* w = W + (size_t)((r * 2 + h) * E_) * E_ + e;
        const float* rb = rel + b * E_;
        float s = hb[(r * 2 + h) * E_ + e];
#pragma unroll 8
        for (int i = 0; i < E_; i++) s += rb[i] * w[(size_t)i * E_];
        g_h[r][h][b][e] = s;
    }
}

// -- per-fact biases + fused scores_0 + fused fp16 fact conversion -----------
// (R13 configuration: 256 blocks x 8 warps, 16 facts/warp)
__global__ void k_cbias(const float* __restrict__ rel, const float* __restrict__ arg1,
                        const float* __restrict__ arg2, const float* __restrict__ fr,
                        const float* __restrict__ fa1, const float* __restrict__ fa2,
                        const int* __restrict__ nbf) {
    int tid = threadIdx.x, lane = tid & 31, hl = lane & 15, sub = lane >> 4;
    int wg = blockIdx.x * 8 + (tid >> 5);  // 0..2047
    int b = wg >> 7;
    int fbase = (wg & 127) * 16;
    const float4* Q;
#define LD2(dst0, dst1, base) Q = (const float4*)(base); float4 dst0 = Q[0], dst1 = Q[1];
    LD2(h00a, h00b, &g_h[0][0][b][hl * 8]);
    LD2(h10a, h10b, &g_h[1][0][b][hl * 8]);
    LD2(h01a, h01b, &g_h[0][1][b][hl * 8]);
    LD2(h11a, h11b, &g_h[1][1][b][hl * 8]);
    LD2(qra, qrb, rel + b * E_ + hl * 8);
    LD2(a1a, a1b, arg1 + b * E_ + hl * 8);
    LD2(a2a, a2b, arg2 + b * E_ + hl * 8);
#undef LD2
    float h00s = dot4(h00a, h00a) + dot4(h00b, h00b);
    float h10s = dot4(h10a, h10a) + dot4(h10b, h10b);
    float h01s = dot4(h01a, h01a) + dot4(h01b, h01b);
    float h11s = dot4(h11a, h11a) + dot4(h11b, h11b);
    float qrs = dot4(qra, qra) + dot4(qrb, qrb);
    float a1s = dot4(a1a, a1a) + dot4(a1b, a1b);
    float a2s = dot4(a2a, a2a) + dot4(a2b, a2b);
    int nb = nbf[b];

    for (int it = 0; it < 8; ++it) {
        int f = fbase + it * 2 + sub;
        size_t off = ((size_t)b * F_ + f) * E_ + hl * 8;
        const float4* PR = (const float4*)(fr + off);
        const float4* P1 = (const float4*)(fa1 + off);
        const float4* P2 = (const float4*)(fa2 + off);
        float4 vr0 = PR[0], vr1 = PR[1];
        float4 v10 = P1[0], v11 = P1[1];
        float4 v20 = P2[0], v21 = P2[1];
        uint4 c1 = {pack_half2(v10.x, v10.y), pack_half2(v10.z, v10.w),
                    pack_half2(v11.x, v11.y), pack_half2(v11.z, v11.w)};
        uint4 c2 = {pack_half2(v20.x, v20.y), pack_half2(v20.z, v20.w),
                    pack_half2(v21.x, v21.y), pack_half2(v21.z, v21.w)};
        *(uint4*)(g_f1hi + off) = c1;
        *(uint4*)(g_f2hi + off) = c2;
        float nsum = dot4(vr0, vr0) + dot4(vr1, vr1) + dot4(v10, v10) + dot4(v11, v11) +
                     dot4(v20, v20) + dot4(v21, v21);
        float a1v1 = dot4(a1a, v10) + dot4(a1b, v11);
        float a2v1 = dot4(a2a, v10) + dot4(a2b, v11);
        float a1v2 = dot4(a1a, v20) + dot4(a1b, v21);
        float a2v2 = dot4(a2a, v20) + dot4(a2b, v21);
        float p0 = nsum + h00s + a1s - 2.f * (dot4(h00a, vr0) + dot4(h00b, vr1) + a1v1);
        float p1 = nsum + h10s + a1s - 2.f * (dot4(h10a, vr0) + dot4(h10b, vr1) + a1v2);
        float q0 = nsum + h01s + a2s - 2.f * (dot4(h01a, vr0) + dot4(h01b, vr1) + a2v2);
        float q1 = nsum + h11s + a2s - 2.f * (dot4(h11a, vr0) + dot4(h11b, vr1) + a2v1);
        float s = nsum + qrs + a1s + a2s -
                  2.f * (dot4(qra, vr0) + dot4(qrb, vr1) + a1v1 + a2v2);
        p0 = hsum16(p0);
        p1 = hsum16(p1);
        q0 = hsum16(q0);
        q1 = hsum16(q1);
        s = hsum16(s);
        if (hl == 0) {
            bool valid = f < nb;
            g_cbias[0][b][f] = valid ? -0.5f * p0 : -3e30f;
            g_cbias[1][b][f] = valid ? -0.5f * p1 : -3e30f;
            g_cb2[0][b][f] = valid ? -0.5f * q0 : -3e30f;
            g_cb2[1][b][f] = valid ? -0.5f * q1 : -3e30f;
            if (valid) atomicMax(&g_s0key[b], fenc(-0.5f * s));
        }
    }
}

// ------- heavy max-plus GEMM via mma.sync (single-pass fp16) -----------------
// grid (nt=16, b=16, r*4+fq=8); 128 threads / 4 warps, CTA tile 128x128,
// warp grid 2m x 2n (warp tile 64x64) -> 0.0625 B/MAC smem traffic
#define OFF_AHI 0
#define OFF_B0 32768
#define OFF_CB 98304
#define SMEM_MG 99328

__global__ __launch_bounds__(128, 2) void k_maxgemm(const int* __restrict__ nbe) {
    extern __shared__ char smem[];
    uint32_t sb = smem_u32(smem);
    const int tid = threadIdx.x, lane = tid & 31, wid = tid >> 5;
    const int wm = (wid & 1) * 64, wn = (wid >> 1) * 64;
    const int nt = blockIdx.x, b = blockIdx.y;
    const int r = blockIdx.z >> 2, fq = blockIdx.z & 3;

    const __half* ehi = g_ehi + ((size_t)b * N_ + nt * 128) * E_;
    const __half* fhi = ((r == 0) ? g_f2hi : g_f1hi) + (size_t)b * F_ * E_;
    const float* cb = &g_cbias[r][b][0];

    // hoisted ldsm row bases + swizzle keys
    uint32_t aBase[4], bOff[4];
    int aX[4], bX[4];
#pragma unroll
    for (int i = 0; i < 4; i++) {
        int row = wm + i * 16 + (lane & 15);
        aBase[i] = sb + OFF_AHI + (uint32_t)row * 256u;
        aX[i] = row & 7;
        int brow = wn + i * 16 + (lane & 15);
        bOff[i] = (uint32_t)brow * 256u;
        bX[i] = brow & 7;
    }

    // resident entity tile (128 rows) via cp.async, swizzled
#pragma unroll
    for (int it = 0; it < 16; ++it) {
        int i = tid + it * 128;
        int row = i >> 4, ch = i & 15;
        cp16(sb + OFF_AHI + swz(row, ch), ehi + (size_t)row * E_ + ch * 8);
    }
    cpcommit();

    auto issueB = [&](int ft, int buf) {
        uint32_t base = sb + OFF_B0 + buf * 32768;
        const __half* sh = fhi + (size_t)ft * 128 * E_;
#pragma unroll
        for (int it = 0; it < 16; ++it) {
            int i = tid + it * 128;
            int row = i >> 4, ch = i & 15;
            cp16(base + swz(row, ch), sh + (size_t)row * E_ + ch * 8);
        }
        if (tid < 32) cp16(sb + OFF_CB + buf * 512 + tid * 16, cb + ft * 128 + tid * 4);
    };
    issueB(fq * 4, 0);
    cpcommit();

    float rmax[8];
#pragma unroll
    for (int i = 0; i < 8; i++) rmax[i] = -3e30f;

    for (int t = 0; t < 4; ++t) {
        cpwait<0>();
        __syncthreads();  // buffer t&1 ready; all warps done with the other buffer
        if (t + 1 < 4) {
            issueB(fq * 4 + t + 1, (t + 1) & 1);
            cpcommit();
        }

        float acc[4][8][4];
#pragma unroll
        for (int i = 0; i < 4; i++)
#pragma unroll
            for (int j = 0; j < 8; j++)
#pragma unroll
                for (int q = 0; q < 4; q++) acc[i][j][q] = 0.f;

        uint32_t bbase = sb + OFF_B0 + (t & 1) * 32768;
#pragma unroll
        for (int ks = 0; ks < 8; ++ks) {
            int kc = ks * 2 + (lane >> 4);
            uint32_t ah[4][4];
#pragma unroll
            for (int i = 0; i < 4; i++)
                ldsm4(ah[i][0], ah[i][1], ah[i][2], ah[i][3],
                      aBase[i] + (uint32_t)((kc ^ aX[i]) << 4));
            uint32_t bh[8][2];
#pragma unroll
            for (int p = 0; p < 4; p++) {
                uint32_t r0, r1, r2, r3;
                ldsm4(r0, r1, r2, r3, bbase + bOff[p] + (uint32_t)((kc ^ bX[p]) << 4));
                bh[2 * p][0] = r0; bh[2 * p][1] = r2;
                bh[2 * p + 1][0] = r1; bh[2 * p + 1][1] = r3;
            }
#pragma unroll
            for (int i = 0; i < 4; i++)
#pragma unroll
                for (int j = 0; j < 8; j++) mma16816(acc[i][j], ah[i], bh[j]);
        }
        // epilogue: add cbias (smem broadcast), fold running row-max
        const float* cbs = (const float*)(smem + OFF_CB + (t & 1) * 512);
#pragma unroll
        for (int j = 0; j < 8; j++) {
            float2 cc = *(const float2*)(cbs + wn + j * 8 + 2 * (lane & 3));
#pragma unroll
            for (int i = 0; i < 4; i++) {
                rmax[2 * i] = fmaxf(rmax[2 * i],
                                    fmaxf(acc[i][j][0] + cc.x, acc[i][j][1] + cc.y));
                rmax[2 * i + 1] = fmaxf(rmax[2 * i + 1],
                                        fmaxf(acc[i][j][2] + cc.x, acc[i][j][3] + cc.y));
            }
        }
    }

    // cross-thread row-max reduction (reuse smem): 8 partials per row
    __syncthreads();
    float* Red = (float*)smem;
#pragma unroll
    for (int i = 0; i < 4; i++)
#pragma unroll
        for (int h = 0; h < 2; h++) {
            int row = wm + i * 16 + h * 8 + (lane >> 2);
            Red[row * 9 + (wid >> 1) * 4 + (lane & 3)] = rmax[2 * i + h];
        }
    __syncthreads();
    // 128 threads cover 128 rows
    {
        float m = -3e30f;
#pragma unroll
        for (int t = 0; t < 8; t++) m = fmaxf(m, Red[tid * 9 + t]);
        int gn = nt * 128 + tid;
        float Lv = m - 0.5f * g_esq[b][gn];
        if (gn < nbe[b]) atomicMax(&g_Lkey[r][b][gn], fenc(Lv));
    }
}

// ---- beam: per-(b,r,z) block — redundant top-K, then hop-2 partial max ------
// (R13 configuration: 256 threads, ZSPLIT=8)
__global__ void k_beam(const float* __restrict__ ent) {
    int b = blockIdx.x, r = blockIdx.y, z = blockIdx.z, tid = threadIdx.x;
    int lane = tid & 31, wid = tid >> 5;
    __shared__ __align__(16) float zs[K_][E_];
    __shared__ __align__(16) float red[K_][257];
    __shared__ float swv[8];
    __shared__ int swi[8];
    __shared__ int schosen;
    __shared__ float szlog[K_];
    __shared__ int szidx[K_];

    // ---- phase 1: top-K over N (identical in every z-block) ----
    float v[8];
#pragma unroll
    for (int j = 0; j < 8; j++) v[j] = fdec(g_Lkey[r][b][tid + 256 * j]);
    for (int kk = 0; kk < K_; kk++) {
        float bv = -3.4e38f;
        int bi = 0;
#pragma unroll
        for (int j = 0; j < 8; j++)
            if (v[j] > bv) { bv = v[j]; bi = tid + 256 * j; }
#pragma unroll
        for (int o = 16; o > 0; o >>= 1) {
            float ov = __shfl_xor_sync(0xffffffffu, bv, o);
            int oi = __shfl_xor_sync(0xffffffffu, bi, o);
            if (ov > bv || (ov == bv && oi < bi)) { bv = ov; bi = oi; }
        }
        if (lane == 0) { swv[wid] = bv; swi[wid] = bi; }
        __syncthreads();
        if (wid == 0) {
            float bv2 = (lane < 8) ? swv[lane] : -3.4e38f;
            int bi2 = (lane < 8) ? swi[lane] : 0;
#pragma unroll
            for (int o = 4; o > 0; o >>= 1) {
                float ov = __shfl_xor_sync(0xffffffffu, bv2, o);
                int oi = __shfl_xor_sync(0xffffffffu, bi2, o);
                if (ov > bv2 || (ov == bv2 && oi < bi2)) { bv2 = ov; bi2 = oi; }
            }
            if (lane == 0) {
                szlog[kk] = bv2;
                szidx[kk] = bi2;
                schosen = bi2;
            }
        }
        __syncthreads();
        int ch = schosen;
        if ((ch & 255) == tid) v[ch >> 8] = -3.4e38f;
        __syncthreads();
    }
    if (z == 0 && tid < K_) {  // publish once for k_final
        g_zidx[r][b][tid] = szidx[tid];
        g_zlog[r][b][tid] = szlog[tid];
    }

    // ---- phase 2: hop-2 partial max over this z-slice of facts ----
    for (int i = tid; i < K_ * E_; i += 256) {
        int k = i >> 7, e = i & 127;
        zs[k][e] = ent[((size_t)b * N_ + szidx[k]) * E_ + e];
    }
    __syncthreads();
    const __half* fy = ((r == 0) ? g_f1hi : g_f2hi) + (size_t)b * F_ * E_;
    int f = z * 256 + tid;
    float c = g_cb2[r][b][f];
    const uint4* row = (const uint4*)(fy + (size_t)f * E_);
    float d[K_];
#pragma unroll
    for (int k = 0; k < K_; k++) d[k] = 0.f;
#pragma unroll 2
    for (int e8 = 0; e8 < 16; e8++) {
        uint4 u = row[e8];
        float2 w0 = __half22float2(*(__half2*)&u.x);
        float2 w1 = __half22float2(*(__half2*)&u.y);
        float2 w2 = __half22float2(*(__half2*)&u.z);
        float2 w3 = __half22float2(*(__half2*)&u.w);
#pragma unroll
        for (int k = 0; k < K_; k++) {
            float4 z0 = ((const float4*)zs[k])[e8 * 2];
            float4 z1 = ((const float4*)zs[k])[e8 * 2 + 1];
            d[k] += w0.x * z0.x + w0.y * z0.y + w1.x * z0.z + w1.y * z0.w +
                    w2.x * z1.x + w2.y * z1.y + w3.x * z1.z + w3.y * z1.w;
        }
    }
#pragma unroll
    for (int k = 0; k < K_; k++) red[k][tid] = d[k] + c;
    __syncthreads();
    for (int k = wid; k < K_; k += 8) {
        float m = -3e30f;
        for (int j = lane; j < 256; j += 32) m = fmaxf(m, red[k][j]);
#pragma unroll
        for (int o = 16; o > 0; o >>= 1) m = fmaxf(m, __shfl_xor_sync(0xffffffffu, m, o));
        if (lane == 0) g_s2part[r][b][z][k] = m;
    }
}

// ---------------- final combine ----------------------------------------------
__global__ void k_final(float* __restrict__ out) {
    int b = threadIdx.x;
    if (b >= B_) return;
    float res = expf(fdec(g_s0key[b]));
#pragma unroll
    for (int r = 0; r < R_; r++)
#pragma unroll
        for (int k = 0; k < K_; k++) {
            float m = -3e30f;
            for (int z = 0; z < ZSPLIT; z++) m = fmaxf(m, g_s2part[r][b][z][k]);
            float s2 = m - 0.5f * g_esq[b][g_zidx[r][b][k]];
            res = fmaxf(res, expf(fminf(s2, g_zlog[r][b][k])));
        }
    out[b] = res;
}

// ---------------- launch -------------------------------------------------------
extern "C" void kernel_launch(void* const* d_in, const int* in_sizes, int n_in,
                              void* d_out, int out_size) {
    (void)in_sizes; (void)n_in; (void)out_size;
    const float* rel = (const float*)d_in[0];
    const float* arg1 = (const float*)d_in[1];
    const float* arg2 = (const float*)d_in[2];
    const float* fr = (const float*)d_in[3];
    const float* fa1 = (const float*)d_in[4];
    const float* fa2 = (const float*)d_in[5];
    const float* ent = (const float*)d_in[6];
    const float* W = (const float*)d_in[7];
    const float* hb = (const float*)d_in[8];
    const int* nbf = (const int*)d_in[9];
    const int* nbe = (const int*)d_in[10];
    float* out = (float*)d_out;

    cudaFuncSetAttribute(k_maxgemm, cudaFuncAttributeMaxDynamicSharedMemorySize, SMEM_MG);

    k_prep<<<4160, 256>>>(ent, rel, W, hb);
    k_cbias<<<256, 256>>>(rel, arg1, arg2, fr, fa1, fa2, nbf);
    k_maxgemm<<<dim3(N_ / 128, B_, 4 * R_), 128, SMEM_MG>>>(nbe);
    k_beam<<<dim3(B_, R_, ZSPLIT), 256>>>(ent);
    k_final<<<1, 32>>>(out);
}

// round 16
// speedup vs baseline: 1.0427x; 1.0271x over previous
#include <cuda_runtime.h>
#include <cuda_fp16.h>
#include <cstdint>

#define B_ 16
#define N_ 2048
#define F_ 2048
#define E_ 128
#define K_ 10
#define R_ 2
#define ZSPLIT 8

// ---------------- device scratch (static, no runtime allocation) ----------
__device__ float g_h[R_][2][B_][E_];        // hop vectors (h1,h2) per rule
__device__ float g_esq[B_][N_];             // entity squared norms
__device__ float g_cbias[R_][B_][F_];       // hop-1 fact bias
__device__ float g_cb2[R_][B_][F_];         // hop-2 fact bias
__device__ unsigned g_s0key[B_];            // scores_0 ordered-int atomic max
__device__ unsigned g_Lkey[R_][B_][N_];     // hop-1 log scores (ordered-uint)
__device__ int   g_zidx[R_][B_][K_];
__device__ float g_zlog[R_][B_][K_];
__device__ float g_s2part[R_][B_][ZSPLIT][K_];

// fp16 planes (round-to-nearest)
__device__ __half g_ehi[B_ * N_ * E_];
__device__ __half g_f1hi[B_ * F_ * E_];
__device__ __half g_f2hi[B_ * F_ * E_];

// ---------------- helpers ---------------------------------------------------
__device__ __forceinline__ float warp_sum(float v) {
#pragma unroll
    for (int o = 16; o > 0; o >>= 1) v += __shfl_xor_sync(0xffffffffu, v, o);
    return v;
}
__device__ __forceinline__ float hsum16(float v) {
#pragma unroll
    for (int o = 8; o > 0; o >>= 1) v += __shfl_xor_sync(0xffffffffu, v, o);
    return v;
}
__device__ __forceinline__ float dot4(float4 a, float4 b) {
    return a.x * b.x + a.y * b.y + a.z * b.z + a.w * b.w;
}
__device__ __forceinline__ unsigned fenc(float v) {
    unsigned u = __float_as_uint(v);
    return (u & 0x80000000u) ? ~u : (u | 0x80000000u);
}
__device__ __forceinline__ float fdec(unsigned k) {
    return (k & 0x80000000u) ? __uint_as_float(k ^ 0x80000000u) : __uint_as_float(~k);
}
__device__ __forceinline__ uint32_t smem_u32(const void* p) {
    uint32_t a;
    asm("{ .reg .u64 t; cvta.to.shared.u64 t, %1; cvt.u32.u64 %0, t; }" : "=r"(a) : "l"(p));
    return a;
}
__device__ __forceinline__ unsigned pack_half2(float a, float b) {
    __half2 h = __halves2half2(__float2half_rn(a), __float2half_rn(b));
    return *(unsigned*)&h;
}

// ---------------- portable tensor-core / async-copy PTX ----------------------
__device__ __forceinline__ void cp16(uint32_t s, const void* g) {
    asm volatile("cp.async.cg.shared.global [%0], [%1], 16;" :: "r"(s), "l"(g));
}
__device__ __forceinline__ void cpcommit() { asm volatile("cp.async.commit_group;"); }
template <int NN>
__device__ __forceinline__ void cpwait() {
    asm volatile("cp.async.wait_group %0;" :: "n"(NN));
}
__device__ __forceinline__ void ldsm4(uint32_t& r0, uint32_t& r1, uint32_t& r2, uint32_t& r3,
                                      uint32_t a) {
    asm volatile("ldmatrix.sync.aligned.m8n8.x4.shared.b16 {%0,%1,%2,%3}, [%4];"
                 : "=r"(r0), "=r"(r1), "=r"(r2), "=r"(r3) : "r"(a));
}
__device__ __forceinline__ void mma16816(float* c, const uint32_t* a, const uint32_t* b) {
    asm volatile(
        "mma.sync.aligned.m16n8k16.row.col.f32.f16.f16.f32 "
        "{%0,%1,%2,%3},{%4,%5,%6,%7},{%8,%9},{%0,%1,%2,%3};"
        : "+f"(c[0]), "+f"(c[1]), "+f"(c[2]), "+f"(c[3])
        : "r"(a[0]), "r"(a[1]), "r"(a[2]), "r"(a[3]), "r"(b[0]), "r"(b[1]));
}
// swizzled tile offset: rows x 128 fp16 (256B rows, 16-byte chunks, XOR swizzle)
__device__ __forceinline__ uint32_t swz(int row, int chunk) {
    return (uint32_t)row * 256u + (uint32_t)((chunk ^ (row & 7)) * 16);
}

// ------ merged prep: entity fp16 + norms + Lkey init, and hop vectors --------
__global__ void k_prep(const float* __restrict__ ent, const float* __restrict__ rel,
                       const float* __restrict__ W, const float* __restrict__ hb) {
    int tid = threadIdx.x;
    if (blockIdx.x < 4096) {
        size_t i = ((size_t)blockIdx.x * 256 + tid) * 4;
        float4 v = *(const float4*)(ent + i);
        uint2 uh = {pack_half2(v.x, v.y), pack_half2(v.z, v.w)};
        *(uint2*)(g_ehi + i) = uh;
        float s = warp_sum(dot4(v, v));
        if ((tid & 31) == 0) {
            int gw = blockIdx.x * 8 + (tid >> 5);
            ((float*)g_esq)[gw] = s;
            unsigned init = fenc(-3e30f);
            int b = gw >> 11, n = gw & (N_ - 1);
            g_Lkey[0][b][n] = init;
            g_Lkey[1][b][n] = init;
        }
    } else {
        int idx = blockIdx.x - 4096;  // 0..63
        int b = idx & 15, h = (idx >> 4) & 1, r = idx >> 5;
        if (tid >= E_) return;
        int e = tid;
        if (e == 0 && h == 0 && r == 0) g_s0key[b] = fenc(-3e30f);
        const float* w = W + (size_t)((r * 2 + h) * E_) * E_ + e;
        const float* rb = rel + b * E_;
        float s = hb[(r * 2 + h) * E_ + e];
#pragma unroll 8
        for (int i = 0; i < E_; i++) s += rb[i] * w[(size_t)i * E_];
        g_h[r][h][b][e] = s;
    }
}

// -- per-fact biases + fused scores_0 + fused fp16 fact conversion -----------
__global__ void k_cbias(const float* __restrict__ rel, const float* __restrict__ arg1,
                        const float* __restrict__ arg2, const float* __restrict__ fr,
                        const float* __restrict__ fa1, const float* __restrict__ fa2,
                        const int* __restrict__ nbf) {
    int tid = threadIdx.x, lane = tid & 31, hl = lane & 15, sub = lane >> 4;
    int wg = blockIdx.x * 8 + (tid >> 5);  // 0..2047
    int b = wg >> 7;
    int fbase = (wg & 127) * 16;
    const float4* Q;
#define LD2(dst0, dst1, base) Q = (const float4*)(base); float4 dst0 = Q[0], dst1 = Q[1];
    LD2(h00a, h00b, &g_h[0][0][b][hl * 8]);
    LD2(h10a, h10b, &g_h[1][0][b][hl * 8]);
    LD2(h01a, h01b, &g_h[0][1][b][hl * 8]);
    LD2(h11a, h11b, &g_h[1][1][b][hl * 8]);
    LD2(qra, qrb, rel + b * E_ + hl * 8);
    LD2(a1a, a1b, arg1 + b * E_ + hl * 8);
    LD2(a2a, a2b, arg2 + b * E_ + hl * 8);
#undef LD2
    float h00s = dot4(h00a, h00a) + dot4(h00b, h00b);
    float h10s = dot4(h10a, h10a) + dot4(h10b, h10b);
    float h01s = dot4(h01a, h01a) + dot4(h01b, h01b);
    float h11s = dot4(h11a, h11a) + dot4(h11b, h11b);
    float qrs = dot4(qra, qra) + dot4(qrb, qrb);
    float a1s = dot4(a1a, a1a) + dot4(a1b, a1b);
    float a2s = dot4(a2a, a2a) + dot4(a2b, a2b);
    int nb = nbf[b];

    for (int it = 0; it < 8; ++it) {
        int f = fbase + it * 2 + sub;
        size_t off = ((size_t)b * F_ + f) * E_ + hl * 8;
        const float4* PR = (const float4*)(fr + off);
        const float4* P1 = (const float4*)(fa1 + off);
        const float4* P2 = (const float4*)(fa2 + off);
        float4 vr0 = PR[0], vr1 = PR[1];
        float4 v10 = P1[0], v11 = P1[1];
        float4 v20 = P2[0], v21 = P2[1];
        uint4 c1 = {pack_half2(v10.x, v10.y), pack_half2(v10.z, v10.w),
                    pack_half2(v11.x, v11.y), pack_half2(v11.z, v11.w)};
        uint4 c2 = {pack_half2(v20.x, v20.y), pack_half2(v20.z, v20.w),
                    pack_half2(v21.x, v21.y), pack_half2(v21.z, v21.w)};
        *(uint4*)(g_f1hi + off) = c1;
        *(uint4*)(g_f2hi + off) = c2;
        float nsum = dot4(vr0, vr0) + dot4(vr1, vr1) + dot4(v10, v10) + dot4(v11, v11) +
                     dot4(v20, v20) + dot4(v21, v21);
        float a1v1 = dot4(a1a, v10) + dot4(a1b, v11);
        float a2v1 = dot4(a2a, v10) + dot4(a2b, v11);
        float a1v2 = dot4(a1a, v20) + dot4(a1b, v21);
        float a2v2 = dot4(a2a, v20) + dot4(a2b, v21);
        float p0 = nsum + h00s + a1s - 2.f * (dot4(h00a, vr0) + dot4(h00b, vr1) + a1v1);
        float p1 = nsum + h10s + a1s - 2.f * (dot4(h10a, vr0) + dot4(h10b, vr1) + a1v2);
        float q0 = nsum + h01s + a2s - 2.f * (dot4(h01a, vr0) + dot4(h01b, vr1) + a2v2);
        float q1 = nsum + h11s + a2s - 2.f * (dot4(h11a, vr0) + dot4(h11b, vr1) + a2v1);
        float s = nsum + qrs + a1s + a2s -
                  2.f * (dot4(qra, vr0) + dot4(qrb, vr1) + a1v1 + a2v2);
        p0 = hsum16(p0);
        p1 = hsum16(p1);
        q0 = hsum16(q0);
        q1 = hsum16(q1);
        s = hsum16(s);
        if (hl == 0) {
            bool valid = f < nb;
            g_cbias[0][b][f] = valid ? -0.5f * p0 : -3e30f;
            g_cbias[1][b][f] = valid ? -0.5f * p1 : -3e30f;
            g_cb2[0][b][f] = valid ? -0.5f * q0 : -3e30f;
            g_cb2[1][b][f] = valid ? -0.5f * q1 : -3e30f;
            if (valid) atomicMax(&g_s0key[b], fenc(-0.5f * s));
        }
    }
}

// ------- heavy max-plus GEMM via mma.sync (single-pass fp16) -----------------
// grid (nt=16, b=16, r*4+fq=8); 256 threads / 8 warps, CTA tile 128x128,
// warp grid 4m x 2n (warp tile 32x64); A + cbias + B all via cp.async
#define OFF_AHI 0
#define OFF_B0 32768
#define OFF_CB 98304
#define SMEM_MG 99328

__global__ __launch_bounds__(256, 2) void k_maxgemm(const int* __restrict__ nbe) {
    extern __shared__ char smem[];
    uint32_t sb = smem_u32(smem);
    const int tid = threadIdx.x, lane = tid & 31, wid = tid >> 5;
    const int wm = (wid & 3) * 32, wn = (wid >> 2) * 64;
    const int nt = blockIdx.x, b = blockIdx.y;
    const int r = blockIdx.z >> 2, fq = blockIdx.z & 3;

    const __half* ehi = g_ehi + ((size_t)b * N_ + nt * 128) * E_;
    const __half* fhi = ((r == 0) ? g_f2hi : g_f1hi) + (size_t)b * F_ * E_;
    const float* cb = &g_cbias[r][b][0];

    // hoisted ldsm row bases + swizzle keys (invariant across k-steps/tiles)
    uint32_t aBase[2], bOff[4];
    int aX[2], bX[4];
#pragma unroll
    for (int i = 0; i < 2; i++) {
        int row = wm + i * 16 + (lane & 15);
        aBase[i] = sb + OFF_AHI + (uint32_t)row * 256u;
        aX[i] = row & 7;
    }
#pragma unroll
    for (int p = 0; p < 4; p++) {
        int row = wn + p * 16 + (lane & 15);
        bOff[p] = (uint32_t)row * 256u;
        bX[p] = row & 7;
    }

    // resident entity tile (128 rows) via cp.async, swizzled
#pragma unroll
    for (int it = 0; it < 8; ++it) {
        int i = tid + it * 256;
        int row = i >> 4, ch = i & 15;
        cp16(sb + OFF_AHI + swz(row, ch), ehi + (size_t)row * E_ + ch * 8);
    }
    cpcommit();

    auto issueB = [&](int ft, int buf) {
        uint32_t base = sb + OFF_B0 + buf * 32768;
        const __half* sh = fhi + (size_t)ft * 128 * E_;
#pragma unroll
        for (int it = 0; it < 8; ++it) {
            int i = tid + it * 256;
            int row = i >> 4, ch = i & 15;
            cp16(base + swz(row, ch), sh + (size_t)row * E_ + ch * 8);
        }
        if (tid < 32) cp16(sb + OFF_CB + buf * 512 + tid * 16, cb + ft * 128 + tid * 4);
    };
    issueB(fq * 4, 0);
    cpcommit();

    float rmax[4];
#pragma unroll
    for (int i = 0; i < 4; i++) rmax[i] = -3e30f;

    for (int t = 0; t < 4; ++t) {
        int ft = fq * 4 + t;
        cpwait<0>();
        __syncthreads();  // buffer t&1 ready; all warps done with the other buffer
        if (t + 1 < 4) {
            issueB(ft + 1, (t + 1) & 1);
            cpcommit();
        }

        float acc[2][8][4];
#pragma unroll
        for (int i = 0; i < 2; i++)
#pragma unroll
            for (int j = 0; j < 8; j++)
#pragma unroll
                for (int q = 0; q < 4; q++) acc[i][j][q] = 0.f;

        uint32_t bbase = sb + OFF_B0 + (t & 1) * 32768;
#pragma unroll
        for (int ks = 0; ks < 8; ++ks) {
            int kc = ks * 2 + (lane >> 4);
            uint32_t ah[2][4];
#pragma unroll
            for (int i = 0; i < 2; i++)
                ldsm4(ah[i][0], ah[i][1], ah[i][2], ah[i][3],
                      aBase[i] + (uint32_t)((kc ^ aX[i]) << 4));
            uint32_t bh[8][2];
#pragma unroll
            for (int p = 0; p < 4; p++) {
                uint32_t r0, r1, r2, r3;
                ldsm4(r0, r1, r2, r3, bbase + bOff[p] + (uint32_t)((kc ^ bX[p]) << 4));
                bh[2 * p][0] = r0; bh[2 * p][1] = r2;
                bh[2 * p + 1][0] = r1; bh[2 * p + 1][1] = r3;
            }
#pragma unroll
            for (int i = 0; i < 2; i++)
#pragma unroll
                for (int j = 0; j < 8; j++) mma16816(acc[i][j], ah[i], bh[j]);
        }
        // epilogue: add cbias (smem broadcast), fold running row-max
        const float* cbs = (const float*)(smem + OFF_CB + (t & 1) * 512);
#pragma unroll
        for (int j = 0; j < 8; j++) {
            float2 cc = *(const float2*)(cbs + wn + j * 8 + 2 * (lane & 3));
#pragma unroll
            for (int i = 0; i < 2; i++) {
                rmax[2 * i] = fmaxf(rmax[2 * i],
                                    fmaxf(acc[i][j][0] + cc.x, acc[i][j][1] + cc.y));
                rmax[2 * i + 1] = fmaxf(rmax[2 * i + 1],
                                        fmaxf(acc[i][j][2] + cc.x, acc[i][j][3] + cc.y));
            }
        }
    }

    // cross-thread row-max reduction (reuse smem): 8 partials per row
    __syncthreads();
    float* Red = (float*)smem;
#pragma unroll
    for (int i = 0; i < 2; i++)
#pragma unroll
        for (int h = 0; h < 2; h++) {
            int row = wm + i * 16 + h * 8 + (lane >> 2);
            Red[row * 9 + (wid >> 2) * 4 + (lane & 3)] = rmax[2 * i + h];
        }
    __syncthreads();
    if (tid < 128) {
        float m = -3e30f;
#pragma unroll
        for (int t = 0; t < 8; t++) m = fmaxf(m, Red[tid * 9 + t]);
        int gn = nt * 128 + tid;
        float Lv = m - 0.5f * g_esq[b][gn];
        if (gn < nbe[b]) atomicMax(&g_Lkey[r][b][gn], fenc(Lv));
    }
}

// ---- beam: per-(b,r,z) block — warp-local top-K merge, then hop-2 partials ---
// 256 threads / 8 warps, ZSPLIT=8; only 2 block barriers in selection
__global__ void k_beam(const float* __restrict__ ent) {
    int b = blockIdx.x, r = blockIdx.y, z = blockIdx.z, tid = threadIdx.x;
    int lane = tid & 31, wid = tid >> 5;
    __shared__ __align__(16) float zs[K_][E_];
    __shared__ __align__(16) float red[K_][257];
    __shared__ float mv[8 * K_];
    __shared__ int mi[8 * K_];
    __shared__ float szlog[K_];
    __shared__ int szidx[K_];

    // ---- phase 1a: warp-local top-K over 256 elements (no block barriers) ----
    float v[8];
#pragma unroll
    for (int j = 0; j < 8; j++) v[j] = fdec(g_Lkey[r][b][wid * 256 + 32 * j + lane]);
    for (int kk = 0; kk < K_; kk++) {
        float bv = -3.4e38f;
        int bi = 0;
#pragma unroll
        for (int j = 0; j < 8; j++)
            if (v[j] > bv) { bv = v[j]; bi = wid * 256 + 32 * j + lane; }
#pragma unroll
        for (int o = 16; o > 0; o >>= 1) {
            float ov = __shfl_xor_sync(0xffffffffu, bv, o);
            int oi = __shfl_xor_sync(0xffffffffu, bi, o);
            if (ov > bv || (ov == bv && oi < bi)) { bv = ov; bi = oi; }
        }
        if (lane == 0) { mv[wid * K_ + kk] = bv; mi[wid * K_ + kk] = bi; }
        int rel0 = bi - wid * 256;
        if ((rel0 & 31) == lane) v[rel0 >> 5] = -3.4e38f;
    }
    __syncthreads();

    // ---- phase 1b: warp 0 merges 80 candidates (3 register slots) ----
    if (wid == 0) {
        float cv0 = mv[lane], cv1 = mv[32 + lane];
        int ci0 = mi[lane], ci1 = mi[32 + lane];
        float cv2 = (lane < 16) ? mv[64 + lane] : -3.4e38f;
        int ci2 = (lane < 16) ? mi[64 + lane] : -1;
        for (int kk = 0; kk < K_; kk++) {
            float bv = cv0;
            int bi = ci0;
            if (cv1 > bv || (cv1 == bv && ci1 < bi)) { bv = cv1; bi = ci1; }
            if (cv2 > bv || (cv2 == bv && ci2 < bi)) { bv = cv2; bi = ci2; }
#pragma unroll
            for (int o = 16; o > 0; o >>= 1) {
                float ov = __shfl_xor_sync(0xffffffffu, bv, o);
                int oi = __shfl_xor_sync(0xffffffffu, bi, o);
                if (ov > bv || (ov == bv && oi < bi)) { bv = ov; bi = oi; }
            }
            if (lane == 0) { szlog[kk] = bv; szidx[kk] = bi; }
            if (ci0 == bi) cv0 = -3.4e38f;
            if (ci1 == bi) cv1 = -3.4e38f;
            if (ci2 == bi) cv2 = -3.4e38f;
        }
    }
    __syncthreads();
    if (z == 0 && tid < K_) {  // publish once for k_final
        g_zidx[r][b][tid] = szidx[tid];
        g_zlog[r][b][tid] = szlog[tid];
    }

    // ---- phase 2: hop-2 partial max over this z-slice of facts ----
    for (int i = tid; i < K_ * E_; i += 256) {
        int k = i >> 7, e = i & 127;
        zs[k][e] = ent[((size_t)b * N_ + szidx[k]) * E_ + e];
    }
    __syncthreads();
    const __half* fy = ((r == 0) ? g_f1hi : g_f2hi) + (size_t)b * F_ * E_;
    int f = z * 256 + tid;
    float c = g_cb2[r][b][f];
    const uint4* row = (const uint4*)(fy + (size_t)f * E_);
    float d[K_];
#pragma unroll
    for (int k = 0; k < K_; k++) d[k] = 0.f;
#pragma unroll 2
    for (int e8 = 0; e8 < 16; e8++) {
        uint4 u = row[e8];
        float2 w0 = __half22float2(*(__half2*)&u.x);
        float2 w1 = __half22float2(*(__half2*)&u.y);
        float2 w2 = __half22float2(*(__half2*)&u.z);
        float2 w3 = __half22float2(*(__half2*)&u.w);
#pragma unroll
        for (int k = 0; k < K_; k++) {
            float4 z0 = ((const float4*)zs[k])[e8 * 2];
            float4 z1 = ((const float4*)zs[k])[e8 * 2 + 1];
            d[k] += w0.x * z0.x + w0.y * z0.y + w1.x * z0.z + w1.y * z0.w +
                    w2.x * z1.x + w2.y * z1.y + w3.x * z1.z + w3.y * z1.w;
        }
    }
#pragma unroll
    for (int k = 0; k < K_; k++) red[k][tid] = d[k] + c;
    __syncthreads();
    for (int k = wid; k < K_; k += 8) {
        float m = -3e30f;
        for (int j = lane; j < 256; j += 32) m = fmaxf(m, red[k][j]);
#pragma unroll
        for (int o = 16; o > 0; o >>= 1) m = fmaxf(m, __shfl_xor_sync(0xffffffffu, m, o));
        if (lane == 0) g_s2part[r][b][z][k] = m;
    }
}

// ---------------- final combine ----------------------------------------------
__global__ void k_final(float* __restrict__ out) {
    int b = threadIdx.x;
    if (b >= B_) return;
    float res = expf(fdec(g_s0key[b]));
#pragma unroll
    for (int r = 0; r < R_; r++)
#pragma unroll
        for (int k = 0; k < K_; k++) {
            float m = -3e30f;
            for (int z = 0; z < ZSPLIT; z++) m = fmaxf(m, g_s2part[r][b][z][k]);
            float s2 = m - 0.5f * g_esq[b][g_zidx[r][b][k]];
            res = fmaxf(res, expf(fminf(s2, g_zlog[r][b][k])));
        }
    out[b] = res;
}

// ---------------- launch -------------------------------------------------------
extern "C" void kernel_launch(void* const* d_in, const int* in_sizes, int n_in,
                              void* d_out, int out_size) {
    (void)in_sizes; (void)n_in; (void)out_size;
    const float* rel = (const float*)d_in[0];
    const float* arg1 = (const float*)d_in[1];
    const float* arg2 = (const float*)d_in[2];
    const float* fr = (const float*)d_in[3];
    const float* fa1 = (const float*)d_in[4];
    const float* fa2 = (const float*)d_in[5];
    const float* ent = (const float*)d_in[6];
    const float* W = (const float*)d_in[7];
    const float* hb = (const float*)d_in[8];
    const int* nbf = (const int*)d_in[9];
    const int* nbe = (const int*)d_in[10];
    float* out = (float*)d_out;

    cudaFuncSetAttribute(k_maxgemm, cudaFuncAttributeMaxDynamicSharedMemorySize, SMEM_MG);

    k_prep<<<4160, 256>>>(ent, rel, W, hb);
    k_cbias<<<256, 256>>>(rel, arg1, arg2, fr, fa1, fa2, nbf);
    k_maxgemm<<<dim3(N_ / 128, B_, 4 * R_), 256, SMEM_MG>>>(nbe);
    k_beam<<<dim3(B_, R_, ZSPLIT), 256>>>(ent);
    k_final<<<1, 32>>>(out);
}

// round 17
// speedup vs baseline: 1.0429x; 1.0002x over previous
#include <cuda_runtime.h>
#include <cuda_fp16.h>
#include <cstdint>

#define B_ 16
#define N_ 2048
#define F_ 2048
#define E_ 128
#define K_ 10
#define R_ 2
#define ZSPLIT 8

// ---------------- device scratch (static, no runtime allocation) ----------
__device__ float g_h[R_][2][B_][E_];        // hop vectors (h1,h2) per rule
__device__ float g_esq[B_][N_];             // entity squared norms
__device__ float g_cbias[R_][B_][F_];       // hop-1 fact bias
__device__ float g_cb2[R_][B_][F_];         // hop-2 fact bias
__device__ unsigned g_s0key[B_];            // scores_0 ordered-int atomic max
__device__ unsigned g_Lkey[R_][B_][N_];     // hop-1 log scores (ordered-uint)
__device__ int   g_zidx[R_][B_][K_];
__device__ float g_zlog[R_][B_][K_];
__device__ float g_s2part[R_][B_][ZSPLIT][K_];

// fp16 planes (round-to-nearest)
__device__ __half g_ehi[B_ * N_ * E_];
__device__ __half g_f1hi[B_ * F_ * E_];
__device__ __half g_f2hi[B_ * F_ * E_];

// ---------------- helpers ---------------------------------------------------
__device__ __forceinline__ float warp_sum(float v) {
#pragma unroll
    for (int o = 16; o > 0; o >>= 1) v += __shfl_xor_sync(0xffffffffu, v, o);
    return v;
}
__device__ __forceinline__ float hsum16(float v) {
#pragma unroll
    for (int o = 8; o > 0; o >>= 1) v += __shfl_xor_sync(0xffffffffu, v, o);
    return v;
}
__device__ __forceinline__ float dot4(float4 a, float4 b) {
    return a.x * b.x + a.y * b.y + a.z * b.z + a.w * b.w;
}
__device__ __forceinline__ unsigned fenc(float v) {
    unsigned u = __float_as_uint(v);
    return (u & 0x80000000u) ? ~u : (u | 0x80000000u);
}
__device__ __forceinline__ float fdec(unsigned k) {
    return (k & 0x80000000u) ? __uint_as_float(k ^ 0x80000000u) : __uint_as_float(~k);
}
__device__ __forceinline__ uint32_t smem_u32(const void* p) {
    uint32_t a;
    asm("{ .reg .u64 t; cvta.to.shared.u64 t, %1; cvt.u32.u64 %0, t; }" : "=r"(a) : "l"(p));
    return a;
}
__device__ __forceinline__ unsigned pack_half2(float a, float b) {
    __half2 h = __halves2half2(__float2half_rn(a), __float2half_rn(b));
    return *(unsigned*)&h;
}

// ---------------- portable tensor-core / async-copy PTX ----------------------
__device__ __forceinline__ void cp16(uint32_t s, const void* g) {
    asm volatile("cp.async.cg.shared.global [%0], [%1], 16;" :: "r"(s), "l"(g));
}
__device__ __forceinline__ void cpcommit() { asm volatile("cp.async.commit_group;"); }
template <int NN>
__device__ __forceinline__ void cpwait() {
    asm volatile("cp.async.wait_group %0;" :: "n"(NN));
}
__device__ __forceinline__ void ldsm4(uint32_t& r0, uint32_t& r1, uint32_t& r2, uint32_t& r3,
                                      uint32_t a) {
    asm volatile("ldmatrix.sync.aligned.m8n8.x4.shared.b16 {%0,%1,%2,%3}, [%4];"
                 : "=r"(r0), "=r"(r1), "=r"(r2), "=r"(r3) : "r"(a));
}
__device__ __forceinline__ void mma16816(float* c, const uint32_t* a, const uint32_t* b) {
    asm volatile(
        "mma.sync.aligned.m16n8k16.row.col.f32.f16.f16.f32 "
        "{%0,%1,%2,%3},{%4,%5,%6,%7},{%8,%9},{%0,%1,%2,%3};"
        : "+f"(c[0]), "+f"(c[1]), "+f"(c[2]), "+f"(c[3])
        : "r"(a[0]), "r"(a[1]), "r"(a[2]), "r"(a[3]), "r"(b[0]), "r"(b[1]));
}
// swizzled tile offset: rows x 256B (16-byte chunks, XOR swizzle)
__device__ __forceinline__ uint32_t swz(int row, int chunk) {
    return (uint32_t)row * 256u + (uint32_t)((chunk ^ (row & 7)) * 16);
}

// ------ merged prep: entity fp16 + norms + Lkey init, and hop vectors --------
__global__ void k_prep(const float* __restrict__ ent, const float* __restrict__ rel,
                       const float* __restrict__ W, const float* __restrict__ hb) {
    int tid = threadIdx.x;
    if (blockIdx.x < 4096) {
        size_t i = ((size_t)blockIdx.x * 256 + tid) * 4;
        float4 v = *(const float4*)(ent + i);
        uint2 uh = {pack_half2(v.x, v.y), pack_half2(v.z, v.w)};
        *(uint2*)(g_ehi + i) = uh;
        float s = warp_sum(dot4(v, v));
        if ((tid & 31) == 0) {
            int gw = blockIdx.x * 8 + (tid >> 5);
            ((float*)g_esq)[gw] = s;
            unsigned init = fenc(-3e30f);
            int b = gw >> 11, n = gw & (N_ - 1);
            g_Lkey[0][b][n] = init;
            g_Lkey[1][b][n] = init;
        }
    } else {
        int idx = blockIdx.x - 4096;  // 0..63
        int b = idx & 15, h = (idx >> 4) & 1, r = idx >> 5;
        if (tid >= E_) return;
        int e = tid;
        if (e == 0 && h == 0 && r == 0) g_s0key[b] = fenc(-3e30f);
        const float* w = W + (size_t)((r * 2 + h) * E_) * E_ + e;
        const float* rb = rel + b * E_;
        float s = hb[(r * 2 + h) * E_ + e];
#pragma unroll 8
        for (int i = 0; i < E_; i++) s += rb[i] * w[(size_t)i * E_];
        g_h[r][h][b][e] = s;
    }
}

// -- per-fact biases + fused scores_0 + fused fp16 fact conversion -----------
__global__ void k_cbias(const float* __restrict__ rel, const float* __restrict__ arg1,
                        const float* __restrict__ arg2, const float* __restrict__ fr,
                        const float* __restrict__ fa1, const float* __restrict__ fa2,
                        const int* __restrict__ nbf) {
    int tid = threadIdx.x, lane = tid & 31, hl = lane & 15, sub = lane >> 4;
    int wg = blockIdx.x * 8 + (tid >> 5);  // 0..2047
    int b = wg >> 7;
    int fbase = (wg & 127) * 16;
    const float4* Q;
#define LD2(dst0, dst1, base) Q = (const float4*)(base); float4 dst0 = Q[0], dst1 = Q[1];
    LD2(h00a, h00b, &g_h[0][0][b][hl * 8]);
    LD2(h10a, h10b, &g_h[1][0][b][hl * 8]);
    LD2(h01a, h01b, &g_h[0][1][b][hl * 8]);
    LD2(h11a, h11b, &g_h[1][1][b][hl * 8]);
    LD2(qra, qrb, rel + b * E_ + hl * 8);
    LD2(a1a, a1b, arg1 + b * E_ + hl * 8);
    LD2(a2a, a2b, arg2 + b * E_ + hl * 8);
#undef LD2
    float h00s = dot4(h00a, h00a) + dot4(h00b, h00b);
    float h10s = dot4(h10a, h10a) + dot4(h10b, h10b);
    float h01s = dot4(h01a, h01a) + dot4(h01b, h01b);
    float h11s = dot4(h11a, h11a) + dot4(h11b, h11b);
    float qrs = dot4(qra, qra) + dot4(qrb, qrb);
    float a1s = dot4(a1a, a1a) + dot4(a1b, a1b);
    float a2s = dot4(a2a, a2a) + dot4(a2b, a2b);
    int nb = nbf[b];

    for (int it = 0; it < 8; ++it) {
        int f = fbase + it * 2 + sub;
        size_t off = ((size_t)b * F_ + f) * E_ + hl * 8;
        const float4* PR = (const float4*)(fr + off);
        const float4* P1 = (const float4*)(fa1 + off);
        const float4* P2 = (const float4*)(fa2 + off);
        float4 vr0 = PR[0], vr1 = PR[1];
        float4 v10 = P1[0], v11 = P1[1];
        float4 v20 = P2[0], v21 = P2[1];
        uint4 c1 = {pack_half2(v10.x, v10.y), pack_half2(v10.z, v10.w),
                    pack_half2(v11.x, v11.y), pack_half2(v11.z, v11.w)};
        uint4 c2 = {pack_half2(v20.x, v20.y), pack_half2(v20.z, v20.w),
                    pack_half2(v21.x, v21.y), pack_half2(v21.z, v21.w)};
        *(uint4*)(g_f1hi + off) = c1;
        *(uint4*)(g_f2hi + off) = c2;
        float nsum = dot4(vr0, vr0) + dot4(vr1, vr1) + dot4(v10, v10) + dot4(v11, v11) +
                     dot4(v20, v20) + dot4(v21, v21);
        float a1v1 = dot4(a1a, v10) + dot4(a1b, v11);
        float a2v1 = dot4(a2a, v10) + dot4(a2b, v11);
        float a1v2 = dot4(a1a, v20) + dot4(a1b, v21);
        float a2v2 = dot4(a2a, v20) + dot4(a2b, v21);
        float p0 = nsum + h00s + a1s - 2.f * (dot4(h00a, vr0) + dot4(h00b, vr1) + a1v1);
        float p1 = nsum + h10s + a1s - 2.f * (dot4(h10a, vr0) + dot4(h10b, vr1) + a1v2);
        float q0 = nsum + h01s + a2s - 2.f * (dot4(h01a, vr0) + dot4(h01b, vr1) + a2v2);
        float q1 = nsum + h11s + a2s - 2.f * (dot4(h11a, vr0) + dot4(h11b, vr1) + a2v1);
        float s = nsum + qrs + a1s + a2s -
                  2.f * (dot4(qra, vr0) + dot4(qrb, vr1) + a1v1 + a2v2);
        p0 = hsum16(p0);
        p1 = hsum16(p1);
        q0 = hsum16(q0);
        q1 = hsum16(q1);
        s = hsum16(s);
        if (hl == 0) {
            bool valid = f < nb;
            g_cbias[0][b][f] = valid ? -0.5f * p0 : -3e30f;
            g_cbias[1][b][f] = valid ? -0.5f * p1 : -3e30f;
            g_cb2[0][b][f] = valid ? -0.5f * q0 : -3e30f;
            g_cb2[1][b][f] = valid ? -0.5f * q1 : -3e30f;
            if (valid) atomicMax(&g_s0key[b], fenc(-0.5f * s));
        }
    }
}

// ------- heavy max-plus GEMM via mma.sync (single-pass fp16) -----------------
// grid (nt=16, b=16, r*4+fq=8); 256 threads / 8 warps, CTA tile 128x128,
// warp grid 4m x 2n (warp tile 32x64); A + cbias + B all via cp.async
#define OFF_AHI 0
#define OFF_B0 32768
#define OFF_CB 98304
#define SMEM_MG 99328

__global__ __launch_bounds__(256, 2) void k_maxgemm(const int* __restrict__ nbe) {
    extern __shared__ char smem[];
    uint32_t sb = smem_u32(smem);
    const int tid = threadIdx.x, lane = tid & 31, wid = tid >> 5;
    const int wm = (wid & 3) * 32, wn = (wid >> 2) * 64;
    const int nt = blockIdx.x, b = blockIdx.y;
    const int r = blockIdx.z >> 2, fq = blockIdx.z & 3;

    const __half* ehi = g_ehi + ((size_t)b * N_ + nt * 128) * E_;
    const __half* fhi = ((r == 0) ? g_f2hi : g_f1hi) + (size_t)b * F_ * E_;
    const float* cb = &g_cbias[r][b][0];

    // hoisted ldsm row bases + swizzle keys (invariant across k-steps/tiles)
    uint32_t aBase[2], bOff[4];
    int aX[2], bX[4];
#pragma unroll
    for (int i = 0; i < 2; i++) {
        int row = wm + i * 16 + (lane & 15);
        aBase[i] = sb + OFF_AHI + (uint32_t)row * 256u;
        aX[i] = row & 7;
    }
#pragma unroll
    for (int p = 0; p < 4; p++) {
        int row = wn + p * 16 + (lane & 15);
        bOff[p] = (uint32_t)row * 256u;
        bX[p] = row & 7;
    }

    // resident entity tile (128 rows) via cp.async, swizzled
#pragma unroll
    for (int it = 0; it < 8; ++it) {
        int i = tid + it * 256;
        int row = i >> 4, ch = i & 15;
        cp16(sb + OFF_AHI + swz(row, ch), ehi + (size_t)row * E_ + ch * 8);
    }
    cpcommit();

    auto issueB = [&](int ft, int buf) {
        uint32_t base = sb + OFF_B0 + buf * 32768;
        const __half* sh = fhi + (size_t)ft * 128 * E_;
#pragma unroll
        for (int it = 0; it < 8; ++it) {
            int i = tid + it * 256;
            int row = i >> 4, ch = i & 15;
            cp16(base + swz(row, ch), sh + (size_t)row * E_ + ch * 8);
        }
        if (tid < 32) cp16(sb + OFF_CB + buf * 512 + tid * 16, cb + ft * 128 + tid * 4);
    };
    issueB(fq * 4, 0);
    cpcommit();

    float rmax[4];
#pragma unroll
    for (int i = 0; i < 4; i++) rmax[i] = -3e30f;

    for (int t = 0; t < 4; ++t) {
        int ft = fq * 4 + t;
        cpwait<0>();
        __syncthreads();  // buffer t&1 ready; all warps done with the other buffer
        if (t + 1 < 4) {
            issueB(ft + 1, (t + 1) & 1);
            cpcommit();
        }

        float acc[2][8][4];
#pragma unroll
        for (int i = 0; i < 2; i++)
#pragma unroll
            for (int j = 0; j < 8; j++)
#pragma unroll
                for (int q = 0; q < 4; q++) acc[i][j][q] = 0.f;

        uint32_t bbase = sb + OFF_B0 + (t & 1) * 32768;
#pragma unroll
        for (int ks = 0; ks < 8; ++ks) {
            int kc = ks * 2 + (lane >> 4);
            uint32_t ah[2][4];
#pragma unroll
            for (int i = 0; i < 2; i++)
                ldsm4(ah[i][0], ah[i][1], ah[i][2], ah[i][3],
                      aBase[i] + (uint32_t)((kc ^ aX[i]) << 4));
            uint32_t bh[8][2];
#pragma unroll
            for (int p = 0; p < 4; p++) {
                uint32_t r0, r1, r2, r3;
                ldsm4(r0, r1, r2, r3, bbase + bOff[p] + (uint32_t)((kc ^ bX[p]) << 4));
                bh[2 * p][0] = r0; bh[2 * p][1] = r2;
                bh[2 * p + 1][0] = r1; bh[2 * p + 1][1] = r3;
            }
#pragma unroll
            for (int i = 0; i < 2; i++)
#pragma unroll
                for (int j = 0; j < 8; j++) mma16816(acc[i][j], ah[i], bh[j]);
        }
        // epilogue: add cbias (smem broadcast), fold running row-max
        const float* cbs = (const float*)(smem + OFF_CB + (t & 1) * 512);
#pragma unroll
        for (int j = 0; j < 8; j++) {
            float2 cc = *(const float2*)(cbs + wn + j * 8 + 2 * (lane & 3));
#pragma unroll
            for (int i = 0; i < 2; i++) {
                rmax[2 * i] = fmaxf(rmax[2 * i],
                                    fmaxf(acc[i][j][0] + cc.x, acc[i][j][1] + cc.y));
                rmax[2 * i + 1] = fmaxf(rmax[2 * i + 1],
                                        fmaxf(acc[i][j][2] + cc.x, acc[i][j][3] + cc.y));
            }
        }
    }

    // cross-thread row-max reduction (reuse smem): 8 partials per row
    __syncthreads();
    float* Red = (float*)smem;
#pragma unroll
    for (int i = 0; i < 2; i++)
#pragma unroll
        for (int h = 0; h < 2; h++) {
            int row = wm + i * 16 + h * 8 + (lane >> 2);
            Red[row * 9 + (wid >> 2) * 4 + (lane & 3)] = rmax[2 * i + h];
        }
    __syncthreads();
    if (tid < 128) {
        float m = -3e30f;
#pragma unroll
        for (int t = 0; t < 8; t++) m = fmaxf(m, Red[tid * 9 + t]);
        int gn = nt * 128 + tid;
        float Lv = m - 0.5f * g_esq[b][gn];
        if (gn < nbe[b]) atomicMax(&g_Lkey[r][b][gn], fenc(Lv));
    }
}

// ---- beam: prefetch fact tile via cp.async, warp-local top-K, hop-2 partials --
// Dynamic smem: [0,64K) swizzled fact tile (256 rows x 256B),
//               [64K, +5K) zs, [+5K, +10.3K) red
#define BM_FT 0
#define BM_ZS 65536
#define BM_RED (65536 + K_ * E_ * 4)
#define SMEM_BEAM (BM_RED + K_ * 257 * 4)

__global__ __launch_bounds__(256, 2) void k_beam(const float* __restrict__ ent) {
    extern __shared__ char dsm[];
    uint32_t sbb = smem_u32(dsm);
    int b = blockIdx.x, r = blockIdx.y, z = blockIdx.z, tid = threadIdx.x;
    int lane = tid & 31, wid = tid >> 5;
    float* zs = (float*)(dsm + BM_ZS);     // [K][E]
    float* red = (float*)(dsm + BM_RED);   // [K][257]
    __shared__ float mv[8 * K_];
    __shared__ int mi[8 * K_];
    __shared__ float szlog[K_];
    __shared__ int szidx[K_];

    // ---- prefetch this block's 256 fact rows (64 KB) — overlaps top-K ----
    const __half* fy = ((r == 0) ? g_f1hi : g_f2hi) + (size_t)b * F_ * E_;
#pragma unroll
    for (int it = 0; it < 16; ++it) {
        int i = tid + it * 256;
        int row = i >> 4, ch = i & 15;
        cp16(sbb + BM_FT + swz(row, ch), fy + (size_t)(z * 256 + row) * E_ + ch * 8);
    }
    cpcommit();

    // ---- phase 1a: warp-local top-K over 256 elements (no block barriers) ----
    float v[8];
#pragma unroll
    for (int j = 0; j < 8; j++) v[j] = fdec(g_Lkey[r][b][wid * 256 + 32 * j + lane]);
    for (int kk = 0; kk < K_; kk++) {
        float bv = -3.4e38f;
        int bi = 0;
#pragma unroll
        for (int j = 0; j < 8; j++)
            if (v[j] > bv) { bv = v[j]; bi = wid * 256 + 32 * j + lane; }
#pragma unroll
        for (int o = 16; o > 0; o >>= 1) {
            float ov = __shfl_xor_sync(0xffffffffu, bv, o);
            int oi = __shfl_xor_sync(0xffffffffu, bi, o);
            if (ov > bv || (ov == bv && oi < bi)) { bv = ov; bi = oi; }
        }
        if (lane == 0) { mv[wid * K_ + kk] = bv; mi[wid * K_ + kk] = bi; }
        int rel0 = bi - wid * 256;
        if ((rel0 & 31) == lane) v[rel0 >> 5] = -3.4e38f;
    }
    __syncthreads();

    // ---- phase 1b: warp 0 merges 80 candidates (3 register slots) ----
    if (wid == 0) {
        float cv0 = mv[lane], cv1 = mv[32 + lane];
        int ci0 = mi[lane], ci1 = mi[32 + lane];
        float cv2 = (lane < 16) ? mv[64 + lane] : -3.4e38f;
        int ci2 = (lane < 16) ? mi[64 + lane] : -1;
        for (int kk = 0; kk < K_; kk++) {
            float bv = cv0;
            int bi = ci0;
            if (cv1 > bv || (cv1 == bv && ci1 < bi)) { bv = cv1; bi = ci1; }
            if (cv2 > bv || (cv2 == bv && ci2 < bi)) { bv = cv2; bi = ci2; }
#pragma unroll
            for (int o = 16; o > 0; o >>= 1) {
                float ov = __shfl_xor_sync(0xffffffffu, bv, o);
                int oi = __shfl_xor_sync(0xffffffffu, bi, o);
                if (ov > bv || (ov == bv && oi < bi)) { bv = ov; bi = oi; }
            }
            if (lane == 0) { szlog[kk] = bv; szidx[kk] = bi; }
            if (ci0 == bi) cv0 = -3.4e38f;
            if (ci1 == bi) cv1 = -3.4e38f;
            if (ci2 == bi) cv2 = -3.4e38f;
        }
    }
    __syncthreads();
    if (z == 0 && tid < K_) {  // publish once for k_final
        g_zidx[r][b][tid] = szidx[tid];
        g_zlog[r][b][tid] = szlog[tid];
    }

    // ---- load beam entity rows, wait for prefetched fact tile ----
    for (int i = tid; i < K_ * E_; i += 256) {
        int k = i >> 7, e = i & 127;
        zs[k * E_ + e] = ent[((size_t)b * N_ + szidx[k]) * E_ + e];
    }
    cpwait<0>();
    __syncthreads();

    // ---- phase 2: hop-2 partial max over this z-slice (fact rows from smem) ----
    int f = z * 256 + tid;
    float c = g_cb2[r][b][f];
    float d[K_];
#pragma unroll
    for (int k = 0; k < K_; k++) d[k] = 0.f;
#pragma unroll 2
    for (int e8 = 0; e8 < 16; e8++) {
        uint4 u = *(const uint4*)(dsm + BM_FT + swz(tid, e8));
        float2 w0 = __half22float2(*(__half2*)&u.x);
        float2 w1 = __half22float2(*(__half2*)&u.y);
        float2 w2 = __half22float2(*(__half2*)&u.z);
        float2 w3 = __half22float2(*(__half2*)&u.w);
#pragma unroll
        for (int k = 0; k < K_; k++) {
            float4 z0 = ((const float4*)(zs + k * E_))[e8 * 2];
            float4 z1 = ((const float4*)(zs + k * E_))[e8 * 2 + 1];
            d[k] += w0.x * z0.x + w0.y * z0.y + w1.x * z0.z + w1.y * z0.w +
                    w2.x * z1.x + w2.y * z1.y + w3.x * z1.z + w3.y * z1.w;
        }
    }
#pragma unroll
    for (int k = 0; k < K_; k++) red[k * 257 + tid] = d[k] + c;
    __syncthreads();
    for (int k = wid; k < K_; k += 8) {
        float m = -3e30f;
        for (int j = lane; j < 256; j += 32) m = fmaxf(m, red[k * 257 + j]);
#pragma unroll
        for (int o = 16; o > 0; o >>= 1) m = fmaxf(m, __shfl_xor_sync(0xffffffffu, m, o));
        if (lane == 0) g_s2part[r][b][z][k] = m;
    }
}

// ---------------- final combine ----------------------------------------------
__global__ void k_final(float* __restrict__ out) {
    int b = threadIdx.x;
    if (b >= B_) return;
    float res = expf(fdec(g_s0key[b]));
#pragma unroll
    for (int r = 0; r < R_; r++)
#pragma unroll
        for (int k = 0; k < K_; k++) {
            float m = -3e30f;
            for (int z = 0; z < ZSPLIT; z++) m = fmaxf(m, g_s2part[r][b][z][k]);
            float s2 = m - 0.5f * g_esq[b][g_zidx[r][b][k]];
            res = fmaxf(res, expf(fminf(s2, g_zlog[r][b][k])));
        }
    out[b] = res;
}

// ---------------- launch -------------------------------------------------------
extern "C" void kernel_launch(void* const* d_in, const int* in_sizes, int n_in,
                              void* d_out, int out_size) {
    (void)in_sizes; (void)n_in; (void)out_size;
    const float* rel = (const float*)d_in[0];
    const float* arg1 = (const float*)d_in[1];
    const float* arg2 = (const float*)d_in[2];
    const float* fr = (const float*)d_in[3];
    const float* fa1 = (const float*)d_in[4];
    const float* fa2 = (const float*)d_in[5];
    const float* ent = (const float*)d_in[6];
    const float* W = (const float*)d_in[7];
    const float* hb = (const float*)d_in[8];
    const int* nbf = (const int*)d_in[9];
    const int* nbe = (const int*)d_in[10];
    float* out = (float*)d_out;

    cudaFuncSetAttribute(k_maxgemm, cudaFuncAttributeMaxDynamicSharedMemorySize, SMEM_MG);
    cudaFuncSetAttribute(k_beam, cudaFuncAttributeMaxDynamicSharedMemorySize, SMEM_BEAM);

    k_prep<<<4160, 256>>>(ent, rel, W, hb);
    k_cbias<<<256, 256>>>(rel, arg1, arg2, fr, fa1, fa2, nbf);
    k_maxgemm<<<dim3(N_ / 128, B_, 4 * R_), 256, SMEM_MG>>>(nbe);
    k_beam<<<dim3(B_, R_, ZSPLIT), 256, SMEM_BEAM>>>(ent);
    k_final<<<1, 32>>>(out);
}